// round 12
// baseline (speedup 1.0000x reference)
#include <cuda_runtime.h>
#include <math.h>

#define K_BINS   8
#define TAIL     3.0f
#define MIN_W    0.001f
#define MIN_H    0.001f
#define MIN_D    0.001f

#define NROWS    8192
#define NDIMS    2048
#define NPAR     (K_BINS * 3 - 1)   // 23

#define TILE_D   64                  // columns per block
#define THREADS  128                 // 32 col-pairs x 4 row slots
#define ROWS_PB  64                  // rows per block (4 slots x 16 rows)

// per-column-block table image (floats):
//   [0,    2048): f4  [bin][par][32] of float4 {invw, c, ih, ich}
//   [2048, 3072): f2  [bin][par][32] of float2 {dlo, s}
//   [3072, 3520): kn  [7][64]
#define TBL_F2   2048
#define TBL_KN   3072
#define TBL_SZ   3520
#define NBLK_D   (NDIMS / TILE_D)    // 32

__device__ float g_tbl[NBLK_D * TBL_SZ];   // 450 KB device scratch

// ---------------- kernel A: build all tables once ----------------
__global__ __launch_bounds__(TILE_D)
void build_tables(const float* __restrict__ params)
{
    const int tid = threadIdx.x;                 // 0..63
    const int c   = blockIdx.x * TILE_D + tid;   // column

    const float* p = params + (size_t)c * NPAR;
    float uw[K_BINS], uh[K_BINS], ud[K_BINS - 1];
    #pragma unroll
    for (int j = 0; j < K_BINS; j++)      uw[j] = p[j];
    #pragma unroll
    for (int j = 0; j < K_BINS; j++)      uh[j] = p[K_BINS + j];
    #pragma unroll
    for (int j = 0; j < K_BINS - 1; j++)  ud[j] = p[2 * K_BINS + j];

    float cw[K_BINS + 1], ch[K_BINS + 1];
    {
        float m = uw[0];
        #pragma unroll
        for (int j = 1; j < K_BINS; j++) m = fmaxf(m, uw[j]);
        float e[K_BINS], ssum = 0.0f;
        #pragma unroll
        for (int j = 0; j < K_BINS; j++) { e[j] = expf(uw[j] - m); ssum += e[j]; }
        float inv_s = 1.0f / ssum;
        float acc = 0.0f;
        cw[0] = -TAIL;
        #pragma unroll
        for (int j = 0; j < K_BINS; j++) {
            float wj = fmaf(1.0f - MIN_W * K_BINS, e[j] * inv_s, MIN_W);
            acc += wj;
            cw[j + 1] = fmaf(2.0f * TAIL, acc, -TAIL);
        }
        cw[K_BINS] = TAIL;
    }
    {
        float m = uh[0];
        #pragma unroll
        for (int j = 1; j < K_BINS; j++) m = fmaxf(m, uh[j]);
        float e[K_BINS], ssum = 0.0f;
        #pragma unroll
        for (int j = 0; j < K_BINS; j++) { e[j] = expf(uh[j] - m); ssum += e[j]; }
        float inv_s = 1.0f / ssum;
        float acc = 0.0f;
        ch[0] = -TAIL;
        #pragma unroll
        for (int j = 0; j < K_BINS; j++) {
            float hj = fmaf(1.0f - MIN_H * K_BINS, e[j] * inv_s, MIN_H);
            acc += hj;
            ch[j + 1] = fmaf(2.0f * TAIL, acc, -TAIL);
        }
        ch[K_BINS] = TAIL;
    }
    float dv[K_BINS + 1];
    dv[0] = 1.0f;                  // MIN_D + softplus(log(exp(1-MIN_D)-1)) == 1
    dv[K_BINS] = 1.0f;
    #pragma unroll
    for (int j = 0; j < K_BINS - 1; j++)
        dv[j + 1] = MIN_D + log1pf(expf(ud[j]));

    float* out = g_tbl + (size_t)blockIdx.x * TBL_SZ;
    const int tx  = tid >> 1;
    const int par = tid & 1;

    #pragma unroll
    for (int j = 0; j < 7; j++) out[TBL_KN + j * TILE_D + tid] = cw[j + 1];

    #pragma unroll
    for (int b = 0; b < K_BINS; b++) {
        const float iw    = cw[b + 1] - cw[b];
        const float ih    = ch[b + 1] - ch[b];
        const float invw  = 1.0f / iw;
        const float delta = ih * invw;
        const float dlo   = dv[b];
        const float s     = dlo + dv[b + 1] - 2.0f * delta;
        const int o4 = ((b * 2 + par) * 32 + tx) * 4;
        out[o4 + 0] = invw;
        out[o4 + 1] = -cw[b] * invw;
        out[o4 + 2] = ih;
        out[o4 + 3] = ch[b];
        const int o2 = TBL_F2 + ((b * 2 + par) * 32 + tx) * 2;
        out[o2 + 0] = dlo;
        out[o2 + 1] = s;
    }
}

// one spline-element evaluation; coff (par*32) must be compile-time
__device__ __forceinline__ void rqs_one(
    const float g,
    const float k0, const float k1, const float k2, const float k3,
    const float k4, const float k5, const float k6,
    const float4* __restrict__ fA, const float2* __restrict__ fB,
    const int coff,
    float& r_o, float& r_l)
{
    const bool p3 = g >= k3;
    const float m1 = p3 ? k5 : k1;
    const bool p2 = g >= m1;
    const float hi = p2 ? k6 : k4;
    const float lo = p2 ? k2 : k0;
    const float m2 = p3 ? hi : lo;
    const bool p1 = g >= m2;
    const int idx = (p3 ? 4 : 0) + (p2 ? 2 : 0) + (p1 ? 1 : 0);

    const float4 A = fA[idx * 64 + coff];   // {invw, c, ih, ich}
    const float2 B = fB[idx * 64 + coff];   // {dlo, s}

    const float delta = A.z * A.x;           // ih * invw
    const float th  = fmaf(g, A.x, A.y);     // theta
    const float th2 = th * th;
    const float t1m = th - th2;              // theta*(1-theta)

    const float den  = fmaf(B.y, t1m, delta);
    const float rden = __fdividef(1.0f, den);

    const float nm = fmaf(delta, th2, B.x * t1m);
    const float o  = fmaf(A.z * nm, rden, A.w);

    const float dmd = delta - B.x;
    const float dn  = fmaf(fmaf(B.y, th, dmd + dmd), th, B.x);
    const float dd  = delta * rden;
    const float l   = __logf(dn * (dd * dd));

    const bool inside = fabsf(g) <= TAIL;
    r_o = inside ? o : g;
    r_l = inside ? l : 0.0f;
}

// ---------------- kernel B: elementwise transform ----------------
__global__ __launch_bounds__(THREADS, 10)
void rqs_kernel(const float* __restrict__ inputs,
                float* __restrict__ out_base)
{
    __shared__ float sm[TBL_SZ];    // 13.75 KB, same image as g_tbl block

    const int tid = threadIdx.x;

    // stage tables: straight coalesced float4 copy (L2-resident source)
    {
        const float4* src = (const float4*)(g_tbl + (size_t)blockIdx.x * TBL_SZ);
        float4* dst = (float4*)sm;
        #pragma unroll
        for (int i = 0; i < 7; i++) {
            const int k = tid + i * THREADS;
            if (k < TBL_SZ / 4) dst[k] = src[k];
        }
    }
    __syncthreads();

    const int tx  = tid & 31;                    // col-pair index
    const int ty  = tid >> 5;                    // row slot 0..3
    const int col = blockIdx.x * TILE_D + 2 * tx;
    const int row0 = blockIdx.y * ROWS_PB + ty;

    // knots for both columns -> named registers
    const float* kn = sm + TBL_KN;
    const float ka0 = kn[0*64 + 2*tx],   ka1 = kn[1*64 + 2*tx],   ka2 = kn[2*64 + 2*tx];
    const float ka3 = kn[3*64 + 2*tx],   ka4 = kn[4*64 + 2*tx],   ka5 = kn[5*64 + 2*tx];
    const float ka6 = kn[6*64 + 2*tx];
    const float kb0 = kn[0*64 + 2*tx+1], kb1 = kn[1*64 + 2*tx+1], kb2 = kn[2*64 + 2*tx+1];
    const float kb3 = kn[3*64 + 2*tx+1], kb4 = kn[4*64 + 2*tx+1], kb5 = kn[5*64 + 2*tx+1];
    const float kb6 = kn[6*64 + 2*tx+1];

    const float4* __restrict__ fA = (const float4*)sm + tx;            // bin stride 64, par 32
    const float2* __restrict__ fB = (const float2*)(sm + TBL_F2) + tx;

    const size_t base = (size_t)row0 * NDIMS + col;
    const float2* __restrict__ pin = (const float2*)(inputs + base);
    float2* __restrict__ po = (float2*)(out_base + base);
    float2* __restrict__ pl = (float2*)(out_base + (size_t)NROWS * NDIMS + base);
    const int RSTRIDE = 4 * NDIMS / 2;           // float2 units per 4-row step

    #pragma unroll 1
    for (int ii = 0; ii < 4; ii++) {
        float2 gv[4];
        #pragma unroll
        for (int j = 0; j < 4; j++) gv[j] = pin[j * RSTRIDE];

        #pragma unroll
        for (int j = 0; j < 4; j++) {
            float2 ro, rl;
            rqs_one(gv[j].x, ka0, ka1, ka2, ka3, ka4, ka5, ka6, fA, fB, 0,  ro.x, rl.x);
            rqs_one(gv[j].y, kb0, kb1, kb2, kb3, kb4, kb5, kb6, fA, fB, 32, ro.y, rl.y);
            po[j * RSTRIDE] = ro;
            pl[j * RSTRIDE] = rl;
        }
        pin += 4 * RSTRIDE;
        po  += 4 * RSTRIDE;
        pl  += 4 * RSTRIDE;
    }
}

extern "C" void kernel_launch(void* const* d_in, const int* in_sizes, int n_in,
                              void* d_out, int out_size)
{
    const float* inputs = (const float*)d_in[0];
    const float* params = (const float*)d_in[1];
    float* out = (float*)d_out;

    build_tables<<<NBLK_D, TILE_D>>>(params);
    dim3 grid(NBLK_D, NROWS / ROWS_PB);   // (32, 128)
    rqs_kernel<<<grid, THREADS>>>(inputs, out);
}

// round 13
// speedup vs baseline: 1.4233x; 1.4233x over previous
#include <cuda_runtime.h>
#include <math.h>

#define K_BINS   8
#define TAIL     3.0f
#define MIN_W    0.001f
#define MIN_H    0.001f
#define MIN_D    0.001f

#define NROWS    8192
#define NDIMS    2048
#define NPAR     (K_BINS * 3 - 1)   // 23

#define TILE_D   64                  // columns per block
#define THREADS  128                 // 32 col-pairs x 4 row slots
#define ROWS_PB  64                  // rows per block (4 slots x 16 rows)

// per-column-block table image (floats):
//   [0,    2048): f4  [bin][par][32] of float4 {invw, c, ih, ich}
//   [2048, 3072): f2  [bin][par][32] of float2 {dlo, s}
//   [3072, 3520): kn  [7][64]
#define TBL_F2   2048
#define TBL_KN   3072
#define TBL_SZ   3520
#define NBLK_D   (NDIMS / TILE_D)    // 32

__device__ __align__(16) float g_tbl[NBLK_D * TBL_SZ];   // 450 KB device scratch

// ---------------- kernel A: build all tables once ----------------
__global__ __launch_bounds__(TILE_D)
void build_tables(const float* __restrict__ params)
{
    const int tid = threadIdx.x;                 // 0..63
    const int c   = blockIdx.x * TILE_D + tid;   // column

    const float* p = params + (size_t)c * NPAR;
    float uw[K_BINS], uh[K_BINS], ud[K_BINS - 1];
    #pragma unroll
    for (int j = 0; j < K_BINS; j++)      uw[j] = p[j];
    #pragma unroll
    for (int j = 0; j < K_BINS; j++)      uh[j] = p[K_BINS + j];
    #pragma unroll
    for (int j = 0; j < K_BINS - 1; j++)  ud[j] = p[2 * K_BINS + j];

    float cw[K_BINS + 1], ch[K_BINS + 1];
    {
        float m = uw[0];
        #pragma unroll
        for (int j = 1; j < K_BINS; j++) m = fmaxf(m, uw[j]);
        float e[K_BINS], ssum = 0.0f;
        #pragma unroll
        for (int j = 0; j < K_BINS; j++) { e[j] = expf(uw[j] - m); ssum += e[j]; }
        float inv_s = 1.0f / ssum;
        float acc = 0.0f;
        cw[0] = -TAIL;
        #pragma unroll
        for (int j = 0; j < K_BINS; j++) {
            float wj = fmaf(1.0f - MIN_W * K_BINS, e[j] * inv_s, MIN_W);
            acc += wj;
            cw[j + 1] = fmaf(2.0f * TAIL, acc, -TAIL);
        }
        cw[K_BINS] = TAIL;
    }
    {
        float m = uh[0];
        #pragma unroll
        for (int j = 1; j < K_BINS; j++) m = fmaxf(m, uh[j]);
        float e[K_BINS], ssum = 0.0f;
        #pragma unroll
        for (int j = 0; j < K_BINS; j++) { e[j] = expf(uh[j] - m); ssum += e[j]; }
        float inv_s = 1.0f / ssum;
        float acc = 0.0f;
        ch[0] = -TAIL;
        #pragma unroll
        for (int j = 0; j < K_BINS; j++) {
            float hj = fmaf(1.0f - MIN_H * K_BINS, e[j] * inv_s, MIN_H);
            acc += hj;
            ch[j + 1] = fmaf(2.0f * TAIL, acc, -TAIL);
        }
        ch[K_BINS] = TAIL;
    }
    float dv[K_BINS + 1];
    dv[0] = 1.0f;                  // MIN_D + softplus(log(exp(1-MIN_D)-1)) == 1
    dv[K_BINS] = 1.0f;
    #pragma unroll
    for (int j = 0; j < K_BINS - 1; j++)
        dv[j + 1] = MIN_D + log1pf(expf(ud[j]));

    float* out = g_tbl + (size_t)blockIdx.x * TBL_SZ;
    const int tx  = tid >> 1;
    const int par = tid & 1;

    #pragma unroll
    for (int j = 0; j < 7; j++) out[TBL_KN + j * TILE_D + tid] = cw[j + 1];

    #pragma unroll
    for (int b = 0; b < K_BINS; b++) {
        const float iw    = cw[b + 1] - cw[b];
        const float ih    = ch[b + 1] - ch[b];
        const float invw  = 1.0f / iw;
        const float delta = ih * invw;
        const float dlo   = dv[b];
        const float s     = dlo + dv[b + 1] - 2.0f * delta;
        const int o4 = ((b * 2 + par) * 32 + tx) * 4;
        out[o4 + 0] = invw;
        out[o4 + 1] = -cw[b] * invw;
        out[o4 + 2] = ih;
        out[o4 + 3] = ch[b];
        const int o2 = TBL_F2 + ((b * 2 + par) * 32 + tx) * 2;
        out[o2 + 0] = dlo;
        out[o2 + 1] = s;
    }
}

// one spline-element evaluation; coff (par*32) must be compile-time
__device__ __forceinline__ void rqs_one(
    const float g,
    const float k0, const float k1, const float k2, const float k3,
    const float k4, const float k5, const float k6,
    const float4* __restrict__ fA, const float2* __restrict__ fB,
    const int coff,
    float& r_o, float& r_l)
{
    const bool p3 = g >= k3;
    const float m1 = p3 ? k5 : k1;
    const bool p2 = g >= m1;
    const float hi = p2 ? k6 : k4;
    const float lo = p2 ? k2 : k0;
    const float m2 = p3 ? hi : lo;
    const bool p1 = g >= m2;
    const int idx = (p3 ? 4 : 0) + (p2 ? 2 : 0) + (p1 ? 1 : 0);

    const float4 A = fA[idx * 64 + coff];   // {invw, c, ih, ich}
    const float2 B = fB[idx * 64 + coff];   // {dlo, s}

    const float delta = A.z * A.x;           // ih * invw
    const float th  = fmaf(g, A.x, A.y);     // theta
    const float th2 = th * th;
    const float t1m = th - th2;              // theta*(1-theta)

    const float den  = fmaf(B.y, t1m, delta);
    const float rden = __fdividef(1.0f, den);

    const float nm = fmaf(delta, th2, B.x * t1m);
    const float o  = fmaf(A.z * nm, rden, A.w);

    const float dmd = delta - B.x;
    const float dn  = fmaf(fmaf(B.y, th, dmd + dmd), th, B.x);
    const float dd  = delta * rden;
    const float l   = __logf(dn * (dd * dd));

    const bool inside = fabsf(g) <= TAIL;
    r_o = inside ? o : g;
    r_l = inside ? l : 0.0f;
}

// ---------------- kernel B: elementwise transform ----------------
__global__ __launch_bounds__(THREADS, 9)
void rqs_kernel(const float* __restrict__ inputs,
                float* __restrict__ out_base)
{
    __shared__ __align__(16) float sm[TBL_SZ];    // 13.75 KB, same image as g_tbl block

    const int tid = threadIdx.x;

    // stage tables: straight coalesced float4 copy (L2-resident source)
    {
        const float4* src = (const float4*)(g_tbl + (size_t)blockIdx.x * TBL_SZ);
        float4* dst = (float4*)sm;
        #pragma unroll
        for (int i = 0; i < 7; i++) {
            const int k = tid + i * THREADS;
            if (k < TBL_SZ / 4) dst[k] = src[k];
        }
    }
    __syncthreads();

    const int tx  = tid & 31;                    // col-pair index
    const int ty  = tid >> 5;                    // row slot 0..3
    const int col = blockIdx.x * TILE_D + 2 * tx;
    const int row0 = blockIdx.y * ROWS_PB + ty;

    // knots for both columns -> named registers
    const float* kn = sm + TBL_KN;
    const float ka0 = kn[0*64 + 2*tx],   ka1 = kn[1*64 + 2*tx],   ka2 = kn[2*64 + 2*tx];
    const float ka3 = kn[3*64 + 2*tx],   ka4 = kn[4*64 + 2*tx],   ka5 = kn[5*64 + 2*tx];
    const float ka6 = kn[6*64 + 2*tx];
    const float kb0 = kn[0*64 + 2*tx+1], kb1 = kn[1*64 + 2*tx+1], kb2 = kn[2*64 + 2*tx+1];
    const float kb3 = kn[3*64 + 2*tx+1], kb4 = kn[4*64 + 2*tx+1], kb5 = kn[5*64 + 2*tx+1];
    const float kb6 = kn[6*64 + 2*tx+1];

    const float4* __restrict__ fA = (const float4*)sm + tx;            // bin stride 64, par 32
    const float2* __restrict__ fB = (const float2*)(sm + TBL_F2) + tx;

    const size_t base = (size_t)row0 * NDIMS + col;
    const float2* __restrict__ pin = (const float2*)(inputs + base);
    float2* __restrict__ po = (float2*)(out_base + base);
    float2* __restrict__ pl = (float2*)(out_base + (size_t)NROWS * NDIMS + base);
    const int RSTRIDE = 4 * NDIMS / 2;           // float2 units per 4-row step

    #pragma unroll 1
    for (int ii = 0; ii < 4; ii++) {
        float2 gv[4];
        #pragma unroll
        for (int j = 0; j < 4; j++) gv[j] = pin[j * RSTRIDE];

        #pragma unroll
        for (int j = 0; j < 4; j++) {
            float2 ro, rl;
            rqs_one(gv[j].x, ka0, ka1, ka2, ka3, ka4, ka5, ka6, fA, fB, 0,  ro.x, rl.x);
            rqs_one(gv[j].y, kb0, kb1, kb2, kb3, kb4, kb5, kb6, fA, fB, 32, ro.y, rl.y);
            po[j * RSTRIDE] = ro;
            pl[j * RSTRIDE] = rl;
        }
        pin += 4 * RSTRIDE;
        po  += 4 * RSTRIDE;
        pl  += 4 * RSTRIDE;
    }
}

extern "C" void kernel_launch(void* const* d_in, const int* in_sizes, int n_in,
                              void* d_out, int out_size)
{
    const float* inputs = (const float*)d_in[0];
    const float* params = (const float*)d_in[1];
    float* out = (float*)d_out;

    build_tables<<<NBLK_D, TILE_D>>>(params);
    dim3 grid(NBLK_D, NROWS / ROWS_PB);   // (32, 128)
    rqs_kernel<<<grid, THREADS>>>(inputs, out);
}